// round 12
// baseline (speedup 1.0000x reference)
#include <cuda_runtime.h>
#include <cuda_fp16.h>
#include <cstdint>

// ---------------------------------------------------------------------------
// PlanStructuredNetwork via warp-level fp16 mma.sync (sm_103-safe baseline PTX).
// 2-term split: x = xh + xl (fp16 pair), w = fp16; fp32 accumulate.
// Each warp owns a 32-row superstrip per weight pass: half P register-resident,
// half Q streamed through a private per-warp SMEM buffer (same-thread
// write/read -> no barriers). Every ldmatrix'd B (weight) fragment feeds 8
// mmas (was 4), halving the SMEM crossbar traffic that bound Round 10.
// ---------------------------------------------------------------------------

#define BATCH 2048
#define NLEAF 1024
#define NW 8    // warps per CTA

__device__ float g_bufA[(size_t)BATCH * NLEAF * 32];       // 256 MB
__device__ float g_bufB[(size_t)BATCH * (NLEAF / 2) * 32]; // 128 MB

__device__ __forceinline__ uint32_t smem_u32(const void* p) {
    uint32_t a;
    asm("{ .reg .u64 t; cvta.to.shared.u64 t, %1; cvt.u32.u64 %0, t; }"
        : "=r"(a) : "l"(p));
    return a;
}

__device__ __forceinline__ void ldsm4(uint32_t addr, uint32_t& r0, uint32_t& r1,
                                      uint32_t& r2, uint32_t& r3) {
    asm volatile("ldmatrix.sync.aligned.m8n8.x4.shared.b16 {%0,%1,%2,%3}, [%4];"
                 : "=r"(r0), "=r"(r1), "=r"(r2), "=r"(r3) : "r"(addr));
}

__device__ __forceinline__ void mma16816(float* d, const uint32_t* a,
                                         uint32_t b0, uint32_t b1) {
    asm volatile(
        "mma.sync.aligned.m16n8k16.row.col.f32.f16.f16.f32 "
        "{%0,%1,%2,%3}, {%4,%5,%6,%7}, {%8,%9}, {%0,%1,%2,%3};"
        : "+f"(d[0]), "+f"(d[1]), "+f"(d[2]), "+f"(d[3])
        : "r"(a[0]), "r"(a[1]), "r"(a[2]), "r"(a[3]), "r"(b0), "r"(b1));
}

// split (a,b) -> fp16 hi pair + fp16 residual-lo pair
__device__ __forceinline__ void pack_split(float a, float b, uint32_t& hi, uint32_t& lo) {
    __half2 hp = __floats2half2_rn(a, b);
    hi = *reinterpret_cast<uint32_t*>(&hp);
    float2 back = __half22float2(hp);
    __half2 lp = __floats2half2_rn(a - back.x, b - back.y);
    lo = *reinterpret_cast<uint32_t*>(&lp);
}

// D(acc) + bias [-> relu] -> next-layer A fragments (hi/lo) in registers.
template <bool RELU>
__device__ __forceinline__ void epi_regs(const float (&acc)[16][4],
                                         uint32_t (&ah)[8][4], uint32_t (&al)[8][4],
                                         const float* __restrict__ bias, int lane4) {
#pragma unroll
    for (int j = 0; j < 16; j++) {
        float2 bb = *(const float2*)(bias + 8 * j + lane4);
        float c0 = acc[j][0] + bb.x, c1 = acc[j][1] + bb.y;
        float c2 = acc[j][2] + bb.x, c3 = acc[j][3] + bb.y;
        if (RELU) {
            c0 = fmaxf(c0, 0.f); c1 = fmaxf(c1, 0.f);
            c2 = fmaxf(c2, 0.f); c3 = fmaxf(c3, 0.f);
        }
        const int s = j >> 1, o = (j & 1) * 2;
        pack_split(c0, c1, ah[s][o], al[s][o]);
        pack_split(c2, c3, ah[s][o + 1], al[s][o + 1]);
    }
}

// Same but stores fragments into the warp's private SMEM stream buffer.
template <bool RELU>
__device__ __forceinline__ void epi_smem(const float (&acc)[16][4],
                                         uint2* __restrict__ qbuf,
                                         const float* __restrict__ bias, int lane4) {
#pragma unroll
    for (int j = 0; j < 16; j++) {
        float2 bb = *(const float2*)(bias + 8 * j + lane4);
        float c0 = acc[j][0] + bb.x, c1 = acc[j][1] + bb.y;
        float c2 = acc[j][2] + bb.x, c3 = acc[j][3] + bb.y;
        if (RELU) {
            c0 = fmaxf(c0, 0.f); c1 = fmaxf(c1, 0.f);
            c2 = fmaxf(c2, 0.f); c3 = fmaxf(c3, 0.f);
        }
        const int s = j >> 1, o = (j & 1) * 2;
        uint32_t h0, l0, h1, l1;
        pack_split(c0, c1, h0, l0);
        pack_split(c2, c3, h1, l1);
        qbuf[(s * 4 + o) * 32]     = make_uint2(h0, l0);
        qbuf[(s * 4 + o + 1) * 32] = make_uint2(h1, l1);
    }
}

// Row base pointers for the gather (join) / direct (leaf) input.
template <int K>
__device__ __forceinline__ void row_ptrs(const float* __restrict__ feats,
                                         const float* __restrict__ prev,
                                         int n, int ln, int offv, long r,
                                         const float*& pa, const float*& pb) {
    if constexpr (K == 32) {
        pa = feats + r * 32;
        pb = nullptr;
    } else {
        int b = (int)(r >> ln), i = (int)(r & (long)(n - 1));
        pa = feats + ((long)b * (NLEAF - 1) + offv + i) * 32;
        pb = prev + ((long)b * n + i) * 64 - 32;  // cols >=32 -> prev
    }
}

template <int K>
__global__ void __launch_bounds__(32 * NW, 1)
mlp_mma(const float* __restrict__ feats, const float* __restrict__ prev,
        const float* __restrict__ gW1, const float* __restrict__ gb1,
        const float* __restrict__ gW2, const float* __restrict__ gb2,
        const float* __restrict__ gW3, const float* __restrict__ gb3,
        float* __restrict__ outp, int n, int ln, int offv, int num_sstrips) {
    constexpr int SA = K + 8;   // halves/row for W1 (odd multiple of 8 -> conflict-free)
    constexpr int S2 = 136;     // halves/row for W2, W3
    constexpr int S1 = K / 16;  // layer-1 k-steps
    constexpr int O_W1 = 0;
    constexpr int O_W2 = O_W1 + 128 * SA;
    constexpr int O_W3 = O_W2 + 128 * S2;
    constexpr int O_BIAS = O_W3 + 32 * S2;                    // halves
    constexpr int O_ACT = ((O_BIAS * 2 + 288 * 4) + 15) & ~15; // bytes

    extern __shared__ __half sh[];
    float* bs = (float*)(sh + O_BIAS);  // [0..127]=b1 [128..255]=b2 [256..287]=b3
    const int tid = threadIdx.x;
    const int lane = tid & 31;
    const int wid = tid >> 5;
    constexpr int NT = 32 * NW;

    // ---- stage weights transposed (Wt[n][k]) as fp16 -----------------------
    for (int idx = tid; idx < 128 * K; idx += NT) {
        int nn = idx & 127, kk = idx >> 7;
        sh[O_W1 + nn * SA + kk] = __float2half(gW1[kk * 128 + nn]);
    }
    for (int idx = tid; idx < 128 * 128; idx += NT) {
        int nn = idx & 127, kk = idx >> 7;
        sh[O_W2 + nn * S2 + kk] = __float2half(gW2[kk * 128 + nn]);
    }
    for (int idx = tid; idx < 32 * 128; idx += NT) {
        int nn = idx & 31, kk = idx >> 5;
        sh[O_W3 + nn * S2 + kk] = __float2half(gW3[kk * 32 + nn]);
    }
    if (tid < 128) { bs[tid] = gb1[tid]; bs[128 + tid] = gb2[tid]; }
    if (tid < 32)  bs[256 + tid] = gb3[tid];
    __syncthreads();

    const uint32_t sb = smem_u32(sh);
    const int lane4 = (lane & 3) * 2;
    // B-ldmatrix lane geometry (mats: n 0-7/8-15 x k 0-7/8-15)
    const int bnr = (lane & 7) + ((lane >> 4) & 1) * 8;
    const int bkb = ((lane >> 3) & 1) * 8;  // halves
    const uint32_t w1b = sb + (O_W1 + bnr * SA + bkb) * 2;
    const uint32_t w2b = sb + (O_W2 + bnr * S2 + bkb) * 2;
    const uint32_t w3b = sb + (O_W3 + bnr * S2 + bkb) * 2;
    // Per-warp Q activation stream buffer: 8 s-steps x 4 regs x 32 lanes x 8B.
    uint2* qbuf = (uint2*)((char*)sh + O_ACT) + (size_t)wid * 1024 + lane;

    float accP[16][4], accQ[16][4];
    uint32_t ah[8][4], al[8][4];

    for (int ss = blockIdx.x * NW + wid; ss < num_sstrips; ss += gridDim.x * NW) {
        const long base = (long)ss * 32;
        const long r0p = base + (lane >> 2);        // P rows: r0p, r0p+8
        const long r0q = base + 16 + (lane >> 2);   // Q rows: r0q, r0q+8

        // ---- layer-1 P fragments -> registers ------------------------------
        uint32_t ahP1[S1][4], alP1[S1][4];
        {
            const float *p0a, *p1a, *p0b, *p1b;
            row_ptrs<K>(feats, prev, n, ln, offv, r0p, p0a, p0b);
            row_ptrs<K>(feats, prev, n, ln, offv, r0p + 8, p1a, p1b);
#pragma unroll
            for (int s = 0; s < S1; s++) {
                const int c = 16 * s + lane4;
                const float* q0 = (c < 32) ? p0a : p0b;
                const float* q1 = (c < 32) ? p1a : p1b;
                float2 v0 = *(const float2*)(q0 + c);
                float2 v1 = *(const float2*)(q1 + c);
                float2 v2 = *(const float2*)(q0 + c + 8);
                float2 v3 = *(const float2*)(q1 + c + 8);
                pack_split(v0.x, v0.y, ahP1[s][0], alP1[s][0]);
                pack_split(v1.x, v1.y, ahP1[s][1], alP1[s][1]);
                pack_split(v2.x, v2.y, ahP1[s][2], alP1[s][2]);
                pack_split(v3.x, v3.y, ahP1[s][3], alP1[s][3]);
            }
        }
        // ---- layer-1 Q fragments -> SMEM stream buffer ---------------------
        {
            const float *p0a, *p1a, *p0b, *p1b;
            row_ptrs<K>(feats, prev, n, ln, offv, r0q, p0a, p0b);
            row_ptrs<K>(feats, prev, n, ln, offv, r0q + 8, p1a, p1b);
#pragma unroll
            for (int s = 0; s < S1; s++) {
                const int c = 16 * s + lane4;
                const float* q0 = (c < 32) ? p0a : p0b;
                const float* q1 = (c < 32) ? p1a : p1b;
                float2 v0 = *(const float2*)(q0 + c);
                float2 v1 = *(const float2*)(q1 + c);
                float2 v2 = *(const float2*)(q0 + c + 8);
                float2 v3 = *(const float2*)(q1 + c + 8);
                uint32_t h, l;
                pack_split(v0.x, v0.y, h, l); qbuf[(s * 4 + 0) * 32] = make_uint2(h, l);
                pack_split(v1.x, v1.y, h, l); qbuf[(s * 4 + 1) * 32] = make_uint2(h, l);
                pack_split(v2.x, v2.y, h, l); qbuf[(s * 4 + 2) * 32] = make_uint2(h, l);
                pack_split(v3.x, v3.y, h, l); qbuf[(s * 4 + 3) * 32] = make_uint2(h, l);
            }
        }

        // ---- layer 1 -------------------------------------------------------
#pragma unroll
        for (int j = 0; j < 16; j++) {
            accP[j][0] = 0.f; accP[j][1] = 0.f; accP[j][2] = 0.f; accP[j][3] = 0.f;
            accQ[j][0] = 0.f; accQ[j][1] = 0.f; accQ[j][2] = 0.f; accQ[j][3] = 0.f;
        }
#pragma unroll
        for (int s = 0; s < S1; s++) {
            uint32_t qh[4], ql[4];
#pragma unroll
            for (int r = 0; r < 4; r++) {
                uint2 v = qbuf[(s * 4 + r) * 32];
                qh[r] = v.x; ql[r] = v.y;
            }
#pragma unroll
            for (int j2 = 0; j2 < 8; j2++) {
                uint32_t b0, b1, b2, b3;
                ldsm4(w1b + (16 * j2 * SA + 16 * s) * 2, b0, b1, b2, b3);
                mma16816(accP[2 * j2],     ahP1[s], b0, b1);
                mma16816(accP[2 * j2 + 1], ahP1[s], b2, b3);
                mma16816(accP[2 * j2],     alP1[s], b0, b1);
                mma16816(accP[2 * j2 + 1], alP1[s], b2, b3);
                mma16816(accQ[2 * j2],     qh, b0, b1);
                mma16816(accQ[2 * j2 + 1], qh, b2, b3);
                mma16816(accQ[2 * j2],     ql, b0, b1);
                mma16816(accQ[2 * j2 + 1], ql, b2, b3);
            }
        }
        epi_regs<true>(accP, ah, al, bs, lane4);
        epi_smem<true>(accQ, qbuf, bs, lane4);

        // ---- layer 2 -------------------------------------------------------
#pragma unroll
        for (int j = 0; j < 16; j++) {
            accP[j][0] = 0.f; accP[j][1] = 0.f; accP[j][2] = 0.f; accP[j][3] = 0.f;
            accQ[j][0] = 0.f; accQ[j][1] = 0.f; accQ[j][2] = 0.f; accQ[j][3] = 0.f;
        }
#pragma unroll
        for (int s = 0; s < 8; s++) {
            uint32_t qh[4], ql[4];
#pragma unroll
            for (int r = 0; r < 4; r++) {
                uint2 v = qbuf[(s * 4 + r) * 32];
                qh[r] = v.x; ql[r] = v.y;
            }
#pragma unroll
            for (int j2 = 0; j2 < 8; j2++) {
                uint32_t b0, b1, b2, b3;
                ldsm4(w2b + (16 * j2 * S2 + 16 * s) * 2, b0, b1, b2, b3);
                mma16816(accP[2 * j2],     ah[s], b0, b1);
                mma16816(accP[2 * j2 + 1], ah[s], b2, b3);
                mma16816(accP[2 * j2],     al[s], b0, b1);
                mma16816(accP[2 * j2 + 1], al[s], b2, b3);
                mma16816(accQ[2 * j2],     qh, b0, b1);
                mma16816(accQ[2 * j2 + 1], qh, b2, b3);
                mma16816(accQ[2 * j2],     ql, b0, b1);
                mma16816(accQ[2 * j2 + 1], ql, b2, b3);
            }
        }
        epi_regs<true>(accP, ah, al, bs + 128, lane4);
        epi_smem<true>(accQ, qbuf, bs + 128, lane4);

        // ---- layer 3: N=32, no relu, fp32 -> global ------------------------
#pragma unroll
        for (int j = 0; j < 4; j++) {
            accP[j][0] = 0.f; accP[j][1] = 0.f; accP[j][2] = 0.f; accP[j][3] = 0.f;
            accQ[j][0] = 0.f; accQ[j][1] = 0.f; accQ[j][2] = 0.f; accQ[j][3] = 0.f;
        }
#pragma unroll
        for (int s = 0; s < 8; s++) {
            uint32_t qh[4], ql[4];
#pragma unroll
            for (int r = 0; r < 4; r++) {
                uint2 v = qbuf[(s * 4 + r) * 32];
                qh[r] = v.x; ql[r] = v.y;
            }
#pragma unroll
            for (int j2 = 0; j2 < 2; j2++) {
                uint32_t b0, b1, b2, b3;
                ldsm4(w3b + (16 * j2 * S2 + 16 * s) * 2, b0, b1, b2, b3);
                mma16816(accP[2 * j2],     ah[s], b0, b1);
                mma16816(accP[2 * j2 + 1], ah[s], b2, b3);
                mma16816(accP[2 * j2],     al[s], b0, b1);
                mma16816(accP[2 * j2 + 1], al[s], b2, b3);
                mma16816(accQ[2 * j2],     qh, b0, b1);
                mma16816(accQ[2 * j2 + 1], qh, b2, b3);
                mma16816(accQ[2 * j2],     ql, b0, b1);
                mma16816(accQ[2 * j2 + 1], ql, b2, b3);
            }
        }
#pragma unroll
        for (int j = 0; j < 4; j++) {
            float2 bb = *(const float2*)(bs + 256 + 8 * j + lane4);
            *(float2*)(outp + r0p * 32 + 8 * j + lane4) =
                make_float2(accP[j][0] + bb.x, accP[j][1] + bb.y);
            *(float2*)(outp + (r0p + 8) * 32 + 8 * j + lane4) =
                make_float2(accP[j][2] + bb.x, accP[j][3] + bb.y);
            *(float2*)(outp + r0q * 32 + 8 * j + lane4) =
                make_float2(accQ[j][0] + bb.x, accQ[j][1] + bb.y);
            *(float2*)(outp + (r0q + 8) * 32 + 8 * j + lane4) =
                make_float2(accQ[j][2] + bb.x, accQ[j][3] + bb.y);
        }
    }
}

__global__ void gather_kernel(const float* __restrict__ src, float* __restrict__ dst) {
    int i = blockIdx.x * blockDim.x + threadIdx.x;
    if (i < BATCH) dst[i] = src[(long)i * 32];
}

static int smem_bytes(int K) {
    int halves = 128 * (K + 8) + 128 * 136 + 32 * 136;
    int o_act = ((halves * 2 + 288 * 4) + 15) & ~15;
    return o_act + NW * 8192;
}

extern "C" void kernel_launch(void* const* d_in, const int* in_sizes, int n_in,
                              void* d_out, int out_size) {
    (void)in_sizes; (void)n_in; (void)out_size;
    const float* leaf_feats     = (const float*)d_in[0];
    const float* internal_feats = (const float*)d_in[1];
    const float* sW1 = (const float*)d_in[2];
    const float* sb1 = (const float*)d_in[3];
    const float* sW2 = (const float*)d_in[4];
    const float* sb2 = (const float*)d_in[5];
    const float* sW3 = (const float*)d_in[6];
    const float* sb3 = (const float*)d_in[7];
    const float* jW1 = (const float*)d_in[8];
    const float* jb1 = (const float*)d_in[9];
    const float* jW2 = (const float*)d_in[10];
    const float* jb2 = (const float*)d_in[11];
    const float* jW3 = (const float*)d_in[12];
    const float* jb3 = (const float*)d_in[13];
    float* out = (float*)d_out;

    float *pa = nullptr, *pb = nullptr;
    cudaGetSymbolAddress((void**)&pa, g_bufA);
    cudaGetSymbolAddress((void**)&pb, g_bufB);

    int dev = 0, sms = 148;
    cudaGetDevice(&dev);
    cudaDeviceGetAttribute(&sms, cudaDevAttrMultiProcessorCount, dev);

    int smem32 = smem_bytes(32), smem96 = smem_bytes(96);
    cudaFuncSetAttribute(mlp_mma<32>, cudaFuncAttributeMaxDynamicSharedMemorySize, smem32);
    cudaFuncSetAttribute(mlp_mma<96>, cudaFuncAttributeMaxDynamicSharedMemorySize, smem96);

    // Leaf level: (B*1024, 32) -> bufA as (B, 1024, 32)
    {
        int sstrips = (BATCH * NLEAF) / 32;
        mlp_mma<32><<<sms, 32 * NW, smem32>>>(leaf_feats, nullptr,
                                              sW1, sb1, sW2, sb2, sW3, sb3,
                                              pa, NLEAF, 10, 0, sstrips);
    }

    // Join levels: n = 512 .. 1
    const float* prev = pa;
    float* curb = pb;
    int off = 0;
    for (int n = NLEAF / 2, ln = 9; n >= 1; n >>= 1, --ln) {
        int sstrips = (BATCH * n) / 32;
        mlp_mma<96><<<sms, 32 * NW, smem96>>>(internal_feats, prev,
                                              jW1, jb1, jW2, jb2, jW3, jb3,
                                              curb, n, ln, off, sstrips);
        off += n;
        const float* tmp = curb;
        curb = (float*)prev;
        prev = tmp;
    }

    gather_kernel<<<(BATCH + 255) / 256, 256>>>(prev, out);
}

// round 13
// speedup vs baseline: 1.2142x; 1.2142x over previous
#include <cuda_runtime.h>
#include <cuda_fp16.h>
#include <cstdint>

// ---------------------------------------------------------------------------
// PlanStructuredNetwork via warp-level fp16 mma.sync (sm_103-safe baseline PTX).
// 2-term split: x = xh + xl (fp16 pair), w = fp16; fp32 accumulate.
// R10 geometry (12 warps, 16-row strips, register-chained L1->L2->L3) plus:
//  - cp.async prefetch of the next strip's input rows into a private per-warp
//    SMEM buffer, overlapped with current-strip L2/L3 compute (no barriers).
//  - j2 processed in groups of 4: ldsm x4 then 8 hi-mmas then 8 lo-mmas,
//    pushing acc-RAW distance from 2 to 8 and decoupling ldsm from consumers.
// ---------------------------------------------------------------------------

#define BATCH 2048
#define NLEAF 1024
#define NW 12   // warps per CTA

__device__ float g_bufA[(size_t)BATCH * NLEAF * 32];       // 256 MB
__device__ float g_bufB[(size_t)BATCH * (NLEAF / 2) * 32]; // 128 MB

__device__ __forceinline__ uint32_t smem_u32(const void* p) {
    uint32_t a;
    asm("{ .reg .u64 t; cvta.to.shared.u64 t, %1; cvt.u32.u64 %0, t; }"
        : "=r"(a) : "l"(p));
    return a;
}

__device__ __forceinline__ void cp16(uint32_t dst, const void* src) {
    asm volatile("cp.async.cg.shared.global [%0], [%1], 16;"
                 :: "r"(dst), "l"(src));
}
__device__ __forceinline__ void cp_commit() {
    asm volatile("cp.async.commit_group;");
}
__device__ __forceinline__ void cp_wait0() {
    asm volatile("cp.async.wait_group 0;");
}

__device__ __forceinline__ void ldsm4(uint32_t addr, uint32_t& r0, uint32_t& r1,
                                      uint32_t& r2, uint32_t& r3) {
    asm volatile("ldmatrix.sync.aligned.m8n8.x4.shared.b16 {%0,%1,%2,%3}, [%4];"
                 : "=r"(r0), "=r"(r1), "=r"(r2), "=r"(r3) : "r"(addr));
}

__device__ __forceinline__ void mma16816(float* d, const uint32_t* a,
                                         uint32_t b0, uint32_t b1) {
    asm volatile(
        "mma.sync.aligned.m16n8k16.row.col.f32.f16.f16.f32 "
        "{%0,%1,%2,%3}, {%4,%5,%6,%7}, {%8,%9}, {%0,%1,%2,%3};"
        : "+f"(d[0]), "+f"(d[1]), "+f"(d[2]), "+f"(d[3])
        : "r"(a[0]), "r"(a[1]), "r"(a[2]), "r"(a[3]), "r"(b0), "r"(b1));
}

// split (a,b) -> fp16 hi pair + fp16 residual-lo pair
__device__ __forceinline__ void pack_split(float a, float b, uint32_t& hi, uint32_t& lo) {
    __half2 hp = __floats2half2_rn(a, b);
    hi = *reinterpret_cast<uint32_t*>(&hp);
    float2 back = __half22float2(hp);
    __half2 lp = __floats2half2_rn(a - back.x, b - back.y);
    lo = *reinterpret_cast<uint32_t*>(&lp);
}

// D(acc) + bias [-> relu] -> next-layer A fragments (hi/lo), registers only.
template <bool RELU>
__device__ __forceinline__ void epi(const float (&acc)[16][4],
                                    uint32_t (&ah)[8][4], uint32_t (&al)[8][4],
                                    const float* __restrict__ bias, int lane4) {
#pragma unroll
    for (int j = 0; j < 16; j++) {
        float2 bb = *(const float2*)(bias + 8 * j + lane4);
        float c0 = acc[j][0] + bb.x, c1 = acc[j][1] + bb.y;
        float c2 = acc[j][2] + bb.x, c3 = acc[j][3] + bb.y;
        if (RELU) {
            c0 = fmaxf(c0, 0.f); c1 = fmaxf(c1, 0.f);
            c2 = fmaxf(c2, 0.f); c3 = fmaxf(c3, 0.f);
        }
        const int s = j >> 1, o = (j & 1) * 2;
        pack_split(c0, c1, ah[s][o], al[s][o]);
        pack_split(c2, c3, ah[s][o + 1], al[s][o + 1]);
    }
}

template <int K>
__global__ void __launch_bounds__(32 * NW, 1)
mlp_mma(const float* __restrict__ feats, const float* __restrict__ prev,
        const float* __restrict__ gW1, const float* __restrict__ gb1,
        const float* __restrict__ gW2, const float* __restrict__ gb2,
        const float* __restrict__ gW3, const float* __restrict__ gb3,
        float* __restrict__ outp, int n, int ln, int offv, int num_strips) {
    constexpr int SA = K + 8;   // halves/row for W1 (odd multiple of 8 -> conflict-free)
    constexpr int S2 = 136;     // halves/row for W2, W3
    constexpr int S1 = K / 16;  // layer-1 k-steps
    constexpr int SW = (K == 32) ? 36 : 100;  // staging row stride (words)
    constexpr int SWB = SW * 4;               // staging row stride (bytes)
    constexpr int O_W1 = 0;
    constexpr int O_W2 = O_W1 + 128 * SA;
    constexpr int O_W3 = O_W2 + 128 * S2;
    constexpr int O_BIAS = O_W3 + 32 * S2;                     // halves
    constexpr int O_ACT = ((O_BIAS * 2 + 288 * 4) + 15) & ~15; // bytes

    extern __shared__ __half sh[];
    float* bs = (float*)(sh + O_BIAS);  // [0..127]=b1 [128..255]=b2 [256..287]=b3
    const int tid = threadIdx.x;
    const int lane = tid & 31;
    const int wid = tid >> 5;
    constexpr int NT = 32 * NW;

    // ---- stage weights transposed (Wt[n][k]) as fp16 -----------------------
    for (int idx = tid; idx < 128 * K; idx += NT) {
        int nn = idx & 127, kk = idx >> 7;
        sh[O_W1 + nn * SA + kk] = __float2half(gW1[kk * 128 + nn]);
    }
    for (int idx = tid; idx < 128 * 128; idx += NT) {
        int nn = idx & 127, kk = idx >> 7;
        sh[O_W2 + nn * S2 + kk] = __float2half(gW2[kk * 128 + nn]);
    }
    for (int idx = tid; idx < 32 * 128; idx += NT) {
        int nn = idx & 31, kk = idx >> 5;
        sh[O_W3 + nn * S2 + kk] = __float2half(gW3[kk * 32 + nn]);
    }
    if (tid < 128) { bs[tid] = gb1[tid]; bs[128 + tid] = gb2[tid]; }
    if (tid < 32)  bs[256 + tid] = gb3[tid];
    __syncthreads();

    const uint32_t sb = smem_u32(sh);
    const int lane4 = (lane & 3) * 2;
    // B-ldmatrix lane geometry (mats: n 0-7/8-15 x k 0-7/8-15)
    const int bnr = (lane & 7) + ((lane >> 4) & 1) * 8;
    const int bkb = ((lane >> 3) & 1) * 8;  // halves
    const uint32_t w1b = sb + (O_W1 + bnr * SA + bkb) * 2;
    const uint32_t w2b = sb + (O_W2 + bnr * S2 + bkb) * 2;
    const uint32_t w3b = sb + (O_W3 + bnr * S2 + bkb) * 2;
    // Per-warp staging buffer: 16 rows x SW words.
    float* stg = (float*)((char*)sh + O_ACT) + (size_t)wid * 16 * SW;
    const uint32_t stg_u32 = smem_u32(stg);

    float acc[16][4];
    uint32_t ah[8][4], al[8][4];

    const int start = blockIdx.x * NW + wid;
    const int stride = gridDim.x * NW;

    // ---- prefetch helper (issues cp.async for one strip's 16 rows) ---------
    auto prefetch = [&](int st) {
        const long base = (long)st * 16;
        if constexpr (K == 32) {
#pragma unroll
            for (int i = 0; i < 4; i++) {
                int idx = lane + 32 * i;
                int row = idx >> 3, c = idx & 7;
                cp16(stg_u32 + row * SWB + c * 16,
                     feats + (base + row) * 32 + c * 4);
            }
        } else {
#pragma unroll
            for (int i = 0; i < 4; i++) {
                int idx = lane + 32 * i;
                int row = idx >> 3, c = idx & 7;
                long r = base + row;
                int b = (int)(r >> ln), ii = (int)(r & (long)(n - 1));
                cp16(stg_u32 + row * SWB + c * 16,
                     feats + ((long)b * (NLEAF - 1) + offv + ii) * 32 + c * 4);
            }
#pragma unroll
            for (int i = 0; i < 8; i++) {
                int idx = lane + 32 * i;
                int row = idx >> 4, c = idx & 15;
                long r = base + row;
                int b = (int)(r >> ln), ii = (int)(r & (long)(n - 1));
                cp16(stg_u32 + row * SWB + 128 + c * 16,
                     prev + ((long)b * n + ii) * 64 + c * 4);
            }
        }
        cp_commit();
    };

    if (start < num_strips) prefetch(start);

    for (int st = start; st < num_strips; st += stride) {
        const long row0g = (long)st * 16;
        const long r0 = row0g + (lane >> 2);
        const int lr = lane >> 2;

        cp_wait0();
        __syncwarp();

        // ---- layer 1: A frags from staging SMEM per k-step -----------------
#pragma unroll
        for (int j = 0; j < 16; j++) {
            acc[j][0] = 0.f; acc[j][1] = 0.f; acc[j][2] = 0.f; acc[j][3] = 0.f;
        }
#pragma unroll
        for (int s = 0; s < S1; s++) {
            const int c = 16 * s + lane4;
            float2 v0 = *(const float2*)(stg + lr * SW + c);
            float2 v1 = *(const float2*)(stg + (lr + 8) * SW + c);
            float2 v2 = *(const float2*)(stg + lr * SW + c + 8);
            float2 v3 = *(const float2*)(stg + (lr + 8) * SW + c + 8);
            uint32_t fh[4], fl[4];
            pack_split(v0.x, v0.y, fh[0], fl[0]);
            pack_split(v1.x, v1.y, fh[1], fl[1]);
            pack_split(v2.x, v2.y, fh[2], fl[2]);
            pack_split(v3.x, v3.y, fh[3], fl[3]);
#pragma unroll
            for (int g = 0; g < 2; g++) {
                uint32_t b[4][4];
#pragma unroll
                for (int jj = 0; jj < 4; jj++)
                    ldsm4(w1b + (16 * (4 * g + jj) * SA + 16 * s) * 2,
                          b[jj][0], b[jj][1], b[jj][2], b[jj][3]);
#pragma unroll
                for (int jj = 0; jj < 4; jj++) {
                    mma16816(acc[2 * (4 * g + jj)],     fh, b[jj][0], b[jj][1]);
                    mma16816(acc[2 * (4 * g + jj) + 1], fh, b[jj][2], b[jj][3]);
                }
#pragma unroll
                for (int jj = 0; jj < 4; jj++) {
                    mma16816(acc[2 * (4 * g + jj)],     fl, b[jj][0], b[jj][1]);
                    mma16816(acc[2 * (4 * g + jj) + 1], fl, b[jj][2], b[jj][3]);
                }
            }
        }
        __syncwarp();                       // all lanes done reading staging
        if (st + stride < num_strips) prefetch(st + stride);
        epi<true>(acc, ah, al, bs, lane4);

        // ---- layer 2 -------------------------------------------------------
#pragma unroll
        for (int j = 0; j < 16; j++) {
            acc[j][0] = 0.f; acc[j][1] = 0.f; acc[j][2] = 0.f; acc[j][3] = 0.f;
        }
#pragma unroll
        for (int s = 0; s < 8; s++) {
#pragma unroll
            for (int g = 0; g < 2; g++) {
                uint32_t b[4][4];
#pragma unroll
                for (int jj = 0; jj < 4; jj++)
                    ldsm4(w2b + (16 * (4 * g + jj) * S2 + 16 * s) * 2,
                          b[jj][0], b[jj][1], b[jj][2], b[jj][3]);
#pragma unroll
                for (int jj = 0; jj < 4; jj++) {
                    mma16816(acc[2 * (4 * g + jj)],     ah[s], b[jj][0], b[jj][1]);
                    mma16816(acc[2 * (4 * g + jj) + 1], ah[s], b[jj][2], b[jj][3]);
                }
#pragma unroll
                for (int jj = 0; jj < 4; jj++) {
                    mma16816(acc[2 * (4 * g + jj)],     al[s], b[jj][0], b[jj][1]);
                    mma16816(acc[2 * (4 * g + jj) + 1], al[s], b[jj][2], b[jj][3]);
                }
            }
        }
        epi<true>(acc, ah, al, bs + 128, lane4);

        // ---- layer 3: N=32, no relu, fp32 -> global ------------------------
#pragma unroll
        for (int j = 0; j < 4; j++) {
            acc[j][0] = 0.f; acc[j][1] = 0.f; acc[j][2] = 0.f; acc[j][3] = 0.f;
        }
#pragma unroll
        for (int s = 0; s < 8; s++) {
            uint32_t b[2][4];
#pragma unroll
            for (int jj = 0; jj < 2; jj++)
                ldsm4(w3b + (16 * jj * S2 + 16 * s) * 2,
                      b[jj][0], b[jj][1], b[jj][2], b[jj][3]);
#pragma unroll
            for (int jj = 0; jj < 2; jj++) {
                mma16816(acc[2 * jj],     ah[s], b[jj][0], b[jj][1]);
                mma16816(acc[2 * jj + 1], ah[s], b[jj][2], b[jj][3]);
            }
#pragma unroll
            for (int jj = 0; jj < 2; jj++) {
                mma16816(acc[2 * jj],     al[s], b[jj][0], b[jj][1]);
                mma16816(acc[2 * jj + 1], al[s], b[jj][2], b[jj][3]);
            }
        }
#pragma unroll
        for (int j = 0; j < 4; j++) {
            float2 bb = *(const float2*)(bs + 256 + 8 * j + lane4);
            *(float2*)(outp + r0 * 32 + 8 * j + lane4) =
                make_float2(acc[j][0] + bb.x, acc[j][1] + bb.y);
            *(float2*)(outp + (r0 + 8) * 32 + 8 * j + lane4) =
                make_float2(acc[j][2] + bb.x, acc[j][3] + bb.y);
        }
    }
}

__global__ void gather_kernel(const float* __restrict__ src, float* __restrict__ dst) {
    int i = blockIdx.x * blockDim.x + threadIdx.x;
    if (i < BATCH) dst[i] = src[(long)i * 32];
}

static int smem_bytes(int K) {
    int halves = 128 * (K + 8) + 128 * 136 + 32 * 136;
    int o_act = ((halves * 2 + 288 * 4) + 15) & ~15;
    int swb = (K == 32) ? 144 : 400;
    return o_act + NW * 16 * swb;
}

extern "C" void kernel_launch(void* const* d_in, const int* in_sizes, int n_in,
                              void* d_out, int out_size) {
    (void)in_sizes; (void)n_in; (void)out_size;
    const float* leaf_feats     = (const float*)d_in[0];
    const float* internal_feats = (const float*)d_in[1];
    const float* sW1 = (const float*)d_in[2];
    const float* sb1 = (const float*)d_in[3];
    const float* sW2 = (const float*)d_in[4];
    const float* sb2 = (const float*)d_in[5];
    const float* sW3 = (const float*)d_in[6];
    const float* sb3 = (const float*)d_in[7];
    const float* jW1 = (const float*)d_in[8];
    const float* jb1 = (const float*)d_in[9];
    const float* jW2 = (const float*)d_in[10];
    const float* jb2 = (const float*)d_in[11];
    const float* jW3 = (const float*)d_in[12];
    const float* jb3 = (const float*)d_in[13];
    float* out = (float*)d_out;

    float *pa = nullptr, *pb = nullptr;
    cudaGetSymbolAddress((void**)&pa, g_bufA);
    cudaGetSymbolAddress((void**)&pb, g_bufB);

    int dev = 0, sms = 148;
    cudaGetDevice(&dev);
    cudaDeviceGetAttribute(&sms, cudaDevAttrMultiProcessorCount, dev);

    int smem32 = smem_bytes(32), smem96 = smem_bytes(96);
    cudaFuncSetAttribute(mlp_mma<32>, cudaFuncAttributeMaxDynamicSharedMemorySize, smem32);
    cudaFuncSetAttribute(mlp_mma<96>, cudaFuncAttributeMaxDynamicSharedMemorySize, smem96);

    // Leaf level: (B*1024, 32) -> bufA as (B, 1024, 32)
    {
        int strips = (BATCH * NLEAF) / 16;
        mlp_mma<32><<<sms, 32 * NW, smem32>>>(leaf_feats, nullptr,
                                              sW1, sb1, sW2, sb2, sW3, sb3,
                                              pa, NLEAF, 10, 0, strips);
    }

    // Join levels: n = 512 .. 1
    const float* prev = pa;
    float* curb = pb;
    int off = 0;
    for (int n = NLEAF / 2, ln = 9; n >= 1; n >>= 1, --ln) {
        int strips = (BATCH * n) / 16;
        mlp_mma<96><<<sms, 32 * NW, smem96>>>(internal_feats, prev,
                                              jW1, jb1, jW2, jb2, jW3, jb3,
                                              curb, n, ln, off, strips);
        off += n;
        const float* tmp = curb;
        curb = (float*)prev;
        prev = tmp;
    }

    gather_kernel<<<(BATCH + 255) / 256, 256>>>(prev, out);
}

// round 16
// speedup vs baseline: 1.2857x; 1.0589x over previous
#include <cuda_runtime.h>
#include <cuda_fp16.h>
#include <cstdint>

// ---------------------------------------------------------------------------
// PlanStructuredNetwork, single persistent kernel (sm_103-safe baseline PTX).
// fp16 mma.sync, 2-term split activations (xh+xl), fp16 weights, fp32 acc.
// ALL 11 levels (leaf + 10 joins) run inside one launch; levels are separated
// by a device-wide monotonic atomic barrier (grid == #SMs, 1 CTA/SM ensured by
// ~198KB dynamic SMEM). Weight staging happens once, not 12 times.
// Per-strip pipeline is Round-13's: cp.async input prefetch, register-chained
// L1->L2->L3, ldsm grouped x4 ahead of 8 hi- then 8 lo-mmas.
// ---------------------------------------------------------------------------

#define BATCH 2048
#define NLEAF 1024
#define NW 12   // warps per CTA

__device__ float g_bufA[(size_t)BATCH * NLEAF * 32];       // 256 MB
__device__ float g_bufB[(size_t)BATCH * (NLEAF / 2) * 32]; // 128 MB
__device__ volatile unsigned g_arrive;

__device__ __forceinline__ uint32_t smem_u32(const void* p) {
    uint32_t a;
    asm("{ .reg .u64 t; cvta.to.shared.u64 t, %1; cvt.u32.u64 %0, t; }"
        : "=r"(a) : "l"(p));
    return a;
}

__device__ __forceinline__ void cp16(uint32_t dst, const void* src) {
    asm volatile("cp.async.cg.shared.global [%0], [%1], 16;"
                 :: "r"(dst), "l"(src));
}
__device__ __forceinline__ void cp_commit() {
    asm volatile("cp.async.commit_group;");
}
__device__ __forceinline__ void cp_wait0() {
    asm volatile("cp.async.wait_group 0;");
}

__device__ __forceinline__ void ldsm4(uint32_t addr, uint32_t& r0, uint32_t& r1,
                                      uint32_t& r2, uint32_t& r3) {
    asm volatile("ldmatrix.sync.aligned.m8n8.x4.shared.b16 {%0,%1,%2,%3}, [%4];"
                 : "=r"(r0), "=r"(r1), "=r"(r2), "=r"(r3) : "r"(addr));
}

__device__ __forceinline__ void mma16816(float* d, const uint32_t* a,
                                         uint32_t b0, uint32_t b1) {
    asm volatile(
        "mma.sync.aligned.m16n8k16.row.col.f32.f16.f16.f32 "
        "{%0,%1,%2,%3}, {%4,%5,%6,%7}, {%8,%9}, {%0,%1,%2,%3};"
        : "+f"(d[0]), "+f"(d[1]), "+f"(d[2]), "+f"(d[3])
        : "r"(a[0]), "r"(a[1]), "r"(a[2]), "r"(a[3]), "r"(b0), "r"(b1));
}

// split (a,b) -> fp16 hi pair + fp16 residual-lo pair
__device__ __forceinline__ void pack_split(float a, float b, uint32_t& hi, uint32_t& lo) {
    __half2 hp = __floats2half2_rn(a, b);
    hi = *reinterpret_cast<uint32_t*>(&hp);
    float2 back = __half22float2(hp);
    __half2 lp = __floats2half2_rn(a - back.x, b - back.y);
    lo = *reinterpret_cast<uint32_t*>(&lp);
}

// D(acc) + bias [-> relu] -> next-layer A fragments (hi/lo), registers only.
template <bool RELU>
__device__ __forceinline__ void epi(const float (&acc)[16][4],
                                    uint32_t (&ah)[8][4], uint32_t (&al)[8][4],
                                    const float* __restrict__ bias, int lane4) {
#pragma unroll
    for (int j = 0; j < 16; j++) {
        float2 bb = *(const float2*)(bias + 8 * j + lane4);
        float c0 = acc[j][0] + bb.x, c1 = acc[j][1] + bb.y;
        float c2 = acc[j][2] + bb.x, c3 = acc[j][3] + bb.y;
        if (RELU) {
            c0 = fmaxf(c0, 0.f); c1 = fmaxf(c1, 0.f);
            c2 = fmaxf(c2, 0.f); c3 = fmaxf(c3, 0.f);
        }
        const int s = j >> 1, o = (j & 1) * 2;
        pack_split(c0, c1, ah[s][o], al[s][o]);
        pack_split(c2, c3, ah[s][o + 1], al[s][o + 1]);
    }
}

// Device-wide barrier #barno (monotonic counter; init kernel resets per replay).
__device__ __forceinline__ void grid_bar(int barno) {
    __syncthreads();
    if (threadIdx.x == 0) {
        __threadfence();
        atomicAdd((unsigned*)&g_arrive, 1u);
        const unsigned target = (unsigned)barno * gridDim.x;
        while (g_arrive < target) __nanosleep(64);
        __threadfence();
    }
    __syncthreads();
}

// ---- one level's strip loop (R13 pipeline) ---------------------------------
template <int K>
__device__ void run_level(const float* __restrict__ feats,
                          const float* __restrict__ prev,
                          float* __restrict__ outp,
                          int n, int ln, int offv, int num_strips,
                          uint32_t sb, int o_w1, int o_w2, int o_w3,
                          const float* __restrict__ bs,
                          float* __restrict__ stg, uint32_t stg_u32, int lane) {
    constexpr int SA = K + 8;   // halves/row for W1 (odd multiple of 8)
    constexpr int S2 = 136;     // halves/row for W2, W3
    constexpr int S1 = K / 16;  // layer-1 k-steps
    constexpr int SW = (K == 32) ? 36 : 100;  // staging row stride (words)
    constexpr int SWB = SW * 4;

    const int lane4 = (lane & 3) * 2;
    const int bnr = (lane & 7) + ((lane >> 4) & 1) * 8;
    const int bkb = ((lane >> 3) & 1) * 8;  // halves
    const uint32_t w1b = sb + (uint32_t)(o_w1 + bnr * SA + bkb) * 2;
    const uint32_t w2b = sb + (uint32_t)(o_w2 + bnr * S2 + bkb) * 2;
    const uint32_t w3b = sb + (uint32_t)(o_w3 + bnr * S2 + bkb) * 2;

    const int wid = threadIdx.x >> 5;
    const int start = blockIdx.x * NW + wid;
    const int stride = gridDim.x * NW;

    float acc[16][4];
    uint32_t ah[8][4], al[8][4];

    auto prefetch = [&](int st) {
        const long base = (long)st * 16;
        if constexpr (K == 32) {
#pragma unroll
            for (int i = 0; i < 4; i++) {
                int idx = lane + 32 * i;
                int row = idx >> 3, c = idx & 7;
                cp16(stg_u32 + row * SWB + c * 16,
                     feats + (base + row) * 32 + c * 4);
            }
        } else {
#pragma unroll
            for (int i = 0; i < 4; i++) {
                int idx = lane + 32 * i;
                int row = idx >> 3, c = idx & 7;
                long r = base + row;
                int b = (int)(r >> ln), ii = (int)(r & (long)(n - 1));
                cp16(stg_u32 + row * SWB + c * 16,
                     feats + ((long)b * (NLEAF - 1) + offv + ii) * 32 + c * 4);
            }
#pragma unroll
            for (int i = 0; i < 8; i++) {
                int idx = lane + 32 * i;
                int row = idx >> 4, c = idx & 15;
                long r = base + row;
                int b = (int)(r >> ln), ii = (int)(r & (long)(n - 1));
                cp16(stg_u32 + row * SWB + 128 + c * 16,
                     prev + ((long)b * n + ii) * 64 + c * 4);
            }
        }
        cp_commit();
    };

    if (start < num_strips) prefetch(start);

    for (int st = start; st < num_strips; st += stride) {
        const long row0g = (long)st * 16;
        const long r0 = row0g + (lane >> 2);
        const int lr = lane >> 2;

        cp_wait0();
        __syncwarp();

        // ---- layer 1 -------------------------------------------------------
#pragma unroll
        for (int j = 0; j < 16; j++) {
            acc[j][0] = 0.f; acc[j][1] = 0.f; acc[j][2] = 0.f; acc[j][3] = 0.f;
        }
#pragma unroll
        for (int s = 0; s < S1; s++) {
            const int c = 16 * s + lane4;
            float2 v0 = *(const float2*)(stg + lr * SW + c);
            float2 v1 = *(const float2*)(stg + (lr + 8) * SW + c);
            float2 v2 = *(const float2*)(stg + lr * SW + c + 8);
            float2 v3 = *(const float2*)(stg + (lr + 8) * SW + c + 8);
            uint32_t fh[4], fl[4];
            pack_split(v0.x, v0.y, fh[0], fl[0]);
            pack_split(v1.x, v1.y, fh[1], fl[1]);
            pack_split(v2.x, v2.y, fh[2], fl[2]);
            pack_split(v3.x, v3.y, fh[3], fl[3]);
#pragma unroll
            for (int g = 0; g < 2; g++) {
                uint32_t b[4][4];
#pragma unroll
                for (int jj = 0; jj < 4; jj++)
                    ldsm4(w1b + (16 * (4 * g + jj) * SA + 16 * s) * 2,
                          b[jj][0], b[jj][1], b[jj][2], b[jj][3]);
#pragma unroll
                for (int jj = 0; jj < 4; jj++) {
                    mma16816(acc[2 * (4 * g + jj)],     fh, b[jj][0], b[jj][1]);
                    mma16816(acc[2 * (4 * g + jj) + 1], fh, b[jj][2], b[jj][3]);
                }
#pragma unroll
                for (int jj = 0; jj < 4; jj++) {
                    mma16816(acc[2 * (4 * g + jj)],     fl, b[jj][0], b[jj][1]);
                    mma16816(acc[2 * (4 * g + jj) + 1], fl, b[jj][2], b[jj][3]);
                }
            }
        }
        __syncwarp();
        if (st + stride < num_strips) prefetch(st + stride);
        epi<true>(acc, ah, al, bs, lane4);

        // ---- layer 2 -------------------------------------------------------
#pragma unroll
        for (int j = 0; j < 16; j++) {
            acc[j][0] = 0.f; acc[j][1] = 0.f; acc[j][2] = 0.f; acc[j][3] = 0.f;
        }
#pragma unroll
        for (int s = 0; s < 8; s++) {
#pragma unroll
            for (int g = 0; g < 2; g++) {
                uint32_t b[4][4];
#pragma unroll
                for (int jj = 0; jj < 4; jj++)
                    ldsm4(w2b + (16 * (4 * g + jj) * S2 + 16 * s) * 2,
                          b[jj][0], b[jj][1], b[jj][2], b[jj][3]);
#pragma unroll
                for (int jj = 0; jj < 4; jj++) {
                    mma16816(acc[2 * (4 * g + jj)],     ah[s], b[jj][0], b[jj][1]);
                    mma16816(acc[2 * (4 * g + jj) + 1], ah[s], b[jj][2], b[jj][3]);
                }
#pragma unroll
                for (int jj = 0; jj < 4; jj++) {
                    mma16816(acc[2 * (4 * g + jj)],     al[s], b[jj][0], b[jj][1]);
                    mma16816(acc[2 * (4 * g + jj) + 1], al[s], b[jj][2], b[jj][3]);
                }
            }
        }
        epi<true>(acc, ah, al, bs + 128, lane4);

        // ---- layer 3: N=32, no relu, fp32 -> global ------------------------
#pragma unroll
        for (int j = 0; j < 4; j++) {
            acc[j][0] = 0.f; acc[j][1] = 0.f; acc[j][2] = 0.f; acc[j][3] = 0.f;
        }
#pragma unroll
        for (int s = 0; s < 8; s++) {
            uint32_t b[2][4];
#pragma unroll
            for (int jj = 0; jj < 2; jj++)
                ldsm4(w3b + (16 * jj * S2 + 16 * s) * 2,
                      b[jj][0], b[jj][1], b[jj][2], b[jj][3]);
#pragma unroll
            for (int jj = 0; jj < 2; jj++) {
                mma16816(acc[2 * jj],     ah[s], b[jj][0], b[jj][1]);
                mma16816(acc[2 * jj + 1], ah[s], b[jj][2], b[jj][3]);
            }
#pragma unroll
            for (int jj = 0; jj < 2; jj++) {
                mma16816(acc[2 * jj],     al[s], b[jj][0], b[jj][1]);
                mma16816(acc[2 * jj + 1], al[s], b[jj][2], b[jj][3]);
            }
        }
#pragma unroll
        for (int j = 0; j < 4; j++) {
            float2 bb = *(const float2*)(bs + 256 + 8 * j + lane4);
            *(float2*)(outp + r0 * 32 + 8 * j + lane4) =
                make_float2(acc[j][0] + bb.x, acc[j][1] + bb.y);
            *(float2*)(outp + (r0 + 8) * 32 + 8 * j + lane4) =
                make_float2(acc[j][2] + bb.x, acc[j][3] + bb.y);
        }
    }
}

// ---- SMEM layout (halves) --------------------------------------------------
#define O_SW1 0
#define O_SW2 5120       /* + 128*40  */
#define O_SW3 22528      /* + 128*136 */
#define O_JW1 26880      /* + 32*136  */
#define O_JW2 40192      /* + 128*104 */
#define O_JW3 57600      /* + 128*136 */
#define O_WEND 61952     /* + 32*136  */
#define O_ACT_B ((O_WEND * 2 + 576 * 4 + 15) & ~15)
#define SMEM_TOTAL (O_ACT_B + NW * 6400)

__global__ void init_bar_kernel() { g_arrive = 0; }

__global__ void __launch_bounds__(32 * NW, 1)
mlp_all(const float* __restrict__ leaf_feats,
        const float* __restrict__ internal_feats,
        const float* __restrict__ sW1, const float* __restrict__ sb1,
        const float* __restrict__ sW2, const float* __restrict__ sb2,
        const float* __restrict__ sW3, const float* __restrict__ sb3,
        const float* __restrict__ jW1, const float* __restrict__ jb1,
        const float* __restrict__ jW2, const float* __restrict__ jb2,
        const float* __restrict__ jW3, const float* __restrict__ jb3) {
    extern __shared__ __half sh[];
    float* bias = (float*)(sh + O_WEND);  // [0:288) leaf set, [288:576) join set
    const int tid = threadIdx.x;
    const int lane = tid & 31;
    const int wid = tid >> 5;
    constexpr int NT = 32 * NW;

    // ---- stage all weights (transposed Wt[n][k]) once ----------------------
    for (int idx = tid; idx < 128 * 32; idx += NT) {
        int nn = idx & 127, kk = idx >> 7;
        sh[O_SW1 + nn * 40 + kk] = __float2half(sW1[kk * 128 + nn]);
    }
    for (int idx = tid; idx < 128 * 128; idx += NT) {
        int nn = idx & 127, kk = idx >> 7;
        sh[O_SW2 + nn * 136 + kk] = __float2half(sW2[kk * 128 + nn]);
    }
    for (int idx = tid; idx < 32 * 128; idx += NT) {
        int nn = idx & 31, kk = idx >> 5;
        sh[O_SW3 + nn * 136 + kk] = __float2half(sW3[kk * 32 + nn]);
    }
    for (int idx = tid; idx < 128 * 96; idx += NT) {
        int nn = idx & 127, kk = idx >> 7;
        sh[O_JW1 + nn * 104 + kk] = __float2half(jW1[kk * 128 + nn]);
    }
    for (int idx = tid; idx < 128 * 128; idx += NT) {
        int nn = idx & 127, kk = idx >> 7;
        sh[O_JW2 + nn * 136 + kk] = __float2half(jW2[kk * 128 + nn]);
    }
    for (int idx = tid; idx < 32 * 128; idx += NT) {
        int nn = idx & 31, kk = idx >> 5;
        sh[O_JW3 + nn * 136 + kk] = __float2half(jW3[kk * 32 + nn]);
    }
    if (tid < 128) {
        bias[tid] = sb1[tid];       bias[128 + tid] = sb2[tid];
        bias[288 + tid] = jb1[tid]; bias[288 + 128 + tid] = jb2[tid];
    }
    if (tid < 32) { bias[256 + tid] = sb3[tid]; bias[288 + 256 + tid] = jb3[tid]; }
    __syncthreads();

    const uint32_t sb = smem_u32(sh);
    float* stg = (float*)((char*)sh + O_ACT_B) + (size_t)wid * 1600;
    const uint32_t stg_u32 = smem_u32(stg);

    // ---- level 0: leaf -----------------------------------------------------
    run_level<32>(leaf_feats, nullptr, g_bufA, NLEAF, 10, 0,
                  (BATCH * NLEAF) / 16, sb, O_SW1, O_SW2, O_SW3,
                  bias, stg, stg_u32, lane);
    int barno = 1;
    grid_bar(barno++);

    // ---- levels 1..10: joins ----------------------------------------------
    const float* pv = g_bufA;
    float* cr = g_bufB;
    int off = 0;
#pragma unroll 1
    for (int n = NLEAF / 2, ln = 9; n >= 1; n >>= 1, --ln) {
        run_level<96>(internal_feats, pv, cr, n, ln, off,
                      (BATCH * n) / 16, sb, O_JW1, O_JW2, O_JW3,
                      bias + 288, stg, stg_u32, lane);
        grid_bar(barno++);
        off += n;
        float* t = cr; cr = (float*)pv; pv = t;
    }
}

__global__ void gather_kernel(const float* __restrict__ src, float* __restrict__ dst) {
    int i = blockIdx.x * blockDim.x + threadIdx.x;
    if (i < BATCH) dst[i] = src[(long)i * 32];
}

extern "C" void kernel_launch(void* const* d_in, const int* in_sizes, int n_in,
                              void* d_out, int out_size) {
    (void)in_sizes; (void)n_in; (void)out_size;
    const float* leaf_feats     = (const float*)d_in[0];
    const float* internal_feats = (const float*)d_in[1];
    const float* sW1 = (const float*)d_in[2];
    const float* sb1 = (const float*)d_in[3];
    const float* sW2 = (const float*)d_in[4];
    const float* sb2 = (const float*)d_in[5];
    const float* sW3 = (const float*)d_in[6];
    const float* sb3 = (const float*)d_in[7];
    const float* jW1 = (const float*)d_in[8];
    const float* jb1 = (const float*)d_in[9];
    const float* jW2 = (const float*)d_in[10];
    const float* jb2 = (const float*)d_in[11];
    const float* jW3 = (const float*)d_in[12];
    const float* jb3 = (const float*)d_in[13];
    float* out = (float*)d_out;

    float* pa = nullptr;
    cudaGetSymbolAddress((void**)&pa, g_bufA);  // 10 swaps -> final output in bufA

    int dev = 0, sms = 148;
    cudaGetDevice(&dev);
    cudaDeviceGetAttribute(&sms, cudaDevAttrMultiProcessorCount, dev);

    cudaFuncSetAttribute(mlp_all, cudaFuncAttributeMaxDynamicSharedMemorySize,
                         SMEM_TOTAL);

    init_bar_kernel<<<1, 1>>>();
    mlp_all<<<sms, 32 * NW, SMEM_TOTAL>>>(leaf_feats, internal_feats,
                                          sW1, sb1, sW2, sb2, sW3, sb3,
                                          jW1, jb1, jW2, jb2, jW3, jb3);
    gather_kernel<<<(BATCH + 255) / 256, 256>>>(pa, out);
}

// round 17
// speedup vs baseline: 1.2951x; 1.0073x over previous
#include <cuda_runtime.h>
#include <cuda_fp16.h>
#include <cstdint>

// ---------------------------------------------------------------------------
// PlanStructuredNetwork, single persistent kernel (sm_103-safe baseline PTX).
// fp16 mma.sync, 2-term split activations (xh+xl), fp16 weights, fp32 acc.
// All 11 levels in one launch (device-wide barrier between levels).
// This round: L2+L3 merged into one pipelined chunk loop (L2 output chunk j2
// == L3 A-fragment for k-step j2), bias pre-initialized accumulators, and
// truncation-based hi/lo split (ALU ops, no cvt round-trip chains).
// ---------------------------------------------------------------------------

#define BATCH 2048
#define NLEAF 1024
#define NW 12   // warps per CTA

__device__ float g_bufA[(size_t)BATCH * NLEAF * 32];       // 256 MB
__device__ float g_bufB[(size_t)BATCH * (NLEAF / 2) * 32]; // 128 MB
__device__ volatile unsigned g_arrive;

__device__ __forceinline__ uint32_t smem_u32(const void* p) {
    uint32_t a;
    asm("{ .reg .u64 t; cvta.to.shared.u64 t, %1; cvt.u32.u64 %0, t; }"
        : "=r"(a) : "l"(p));
    return a;
}

__device__ __forceinline__ void cp16(uint32_t dst, const void* src) {
    asm volatile("cp.async.cg.shared.global [%0], [%1], 16;"
                 :: "r"(dst), "l"(src));
}
__device__ __forceinline__ void cp_commit() {
    asm volatile("cp.async.commit_group;");
}
__device__ __forceinline__ void cp_wait0() {
    asm volatile("cp.async.wait_group 0;");
}

__device__ __forceinline__ void ldsm4(uint32_t addr, uint32_t& r0, uint32_t& r1,
                                      uint32_t& r2, uint32_t& r3) {
    asm volatile("ldmatrix.sync.aligned.m8n8.x4.shared.b16 {%0,%1,%2,%3}, [%4];"
                 : "=r"(r0), "=r"(r1), "=r"(r2), "=r"(r3) : "r"(addr));
}

__device__ __forceinline__ void mma16816(float* d, const uint32_t* a,
                                         uint32_t b0, uint32_t b1) {
    asm volatile(
        "mma.sync.aligned.m16n8k16.row.col.f32.f16.f16.f32 "
        "{%0,%1,%2,%3}, {%4,%5,%6,%7}, {%8,%9}, {%0,%1,%2,%3};"
        : "+f"(d[0]), "+f"(d[1]), "+f"(d[2]), "+f"(d[3])
        : "r"(a[0]), "r"(a[1]), "r"(a[2]), "r"(a[3]), "r"(b0), "r"(b1));
}

// Truncation split: hi = x with low 13 mantissa bits cleared (exact in fp16),
// lo = x - hi. ALU-only chain (no cvt round-trip); xh+xl == x to ~2^-21.
__device__ __forceinline__ void split_mask(float a, float b, uint32_t& hi, uint32_t& lo) {
    float ta = __uint_as_float(__float_as_uint(a) & 0xFFFFE000u);
    float tb = __uint_as_float(__float_as_uint(b) & 0xFFFFE000u);
    __half2 hp = __floats2half2_rn(ta, tb);
    hi = *reinterpret_cast<uint32_t*>(&hp);
    __half2 lp = __floats2half2_rn(a - ta, b - tb);
    lo = *reinterpret_cast<uint32_t*>(&lp);
}

// Device-wide barrier #barno (monotonic counter; init kernel resets per replay).
__device__ __forceinline__ void grid_bar(int barno) {
    __syncthreads();
    if (threadIdx.x == 0) {
        __threadfence();
        atomicAdd((unsigned*)&g_arrive, 1u);
        const unsigned target = (unsigned)barno * gridDim.x;
        while (g_arrive < target) __nanosleep(64);
        __threadfence();
    }
    __syncthreads();
}

// ---- one level's strip loop -------------------------------------------------
template <int K>
__device__ void run_level(const float* __restrict__ feats,
                          const float* __restrict__ prev,
                          float* __restrict__ outp,
                          int n, int ln, int offv, int num_strips,
                          uint32_t sb, int o_w1, int o_w2, int o_w3,
                          const float* __restrict__ bs,
                          float* __restrict__ stg, uint32_t stg_u32, int lane) {
    constexpr int SA = K + 8;   // halves/row for W1 (odd multiple of 8)
    constexpr int S2 = 136;     // halves/row for W2, W3
    constexpr int S1 = K / 16;  // layer-1 k-steps
    constexpr int SW = (K == 32) ? 36 : 100;  // staging row stride (words)
    constexpr int SWB = SW * 4;

    const int lane4 = (lane & 3) * 2;
    const int bnr = (lane & 7) + ((lane >> 4) & 1) * 8;
    const int bkb = ((lane >> 3) & 1) * 8;  // halves
    const uint32_t w1b = sb + (uint32_t)(o_w1 + bnr * SA + bkb) * 2;
    const uint32_t w2b = sb + (uint32_t)(o_w2 + bnr * S2 + bkb) * 2;
    const uint32_t w3b = sb + (uint32_t)(o_w3 + bnr * S2 + bkb) * 2;

    const int wid = threadIdx.x >> 5;
    const int start = blockIdx.x * NW + wid;
    const int stride = gridDim.x * NW;

    auto prefetch = [&](int st) {
        const long base = (long)st * 16;
        if constexpr (K == 32) {
#pragma unroll
            for (int i = 0; i < 4; i++) {
                int idx = lane + 32 * i;
                int row = idx >> 3, c = idx & 7;
                cp16(stg_u32 + row * SWB + c * 16,
                     feats + (base + row) * 32 + c * 4);
            }
        } else {
#pragma unroll
            for (int i = 0; i < 4; i++) {
                int idx = lane + 32 * i;
                int row = idx >> 3, c = idx & 7;
                long r = base + row;
                int b = (int)(r >> ln), ii = (int)(r & (long)(n - 1));
                cp16(stg_u32 + row * SWB + c * 16,
                     feats + ((long)b * (NLEAF - 1) + offv + ii) * 32 + c * 4);
            }
#pragma unroll
            for (int i = 0; i < 8; i++) {
                int idx = lane + 32 * i;
                int row = idx >> 4, c = idx & 15;
                long r = base + row;
                int b = (int)(r >> ln), ii = (int)(r & (long)(n - 1));
                cp16(stg_u32 + row * SWB + 128 + c * 16,
                     prev + ((long)b * n + ii) * 64 + c * 4);
            }
        }
        cp_commit();
    };

    if (start < num_strips) prefetch(start);

    for (int st = start; st < num_strips; st += stride) {
        const long row0g = (long)st * 16;
        const long r0 = row0g + (lane >> 2);
        const int lr = lane >> 2;

        cp_wait0();
        __syncwarp();

        // ---- layer 1 (acc pre-initialized with bias1) ----------------------
        float acc[16][4];
#pragma unroll
        for (int j = 0; j < 16; j++) {
            float2 bb = *(const float2*)(bs + 8 * j + lane4);
            acc[j][0] = bb.x; acc[j][1] = bb.y;
            acc[j][2] = bb.x; acc[j][3] = bb.y;
        }
#pragma unroll
        for (int s = 0; s < S1; s++) {
            const int c = 16 * s + lane4;
            float2 v0 = *(const float2*)(stg + lr * SW + c);
            float2 v1 = *(const float2*)(stg + (lr + 8) * SW + c);
            float2 v2 = *(const float2*)(stg + lr * SW + c + 8);
            float2 v3 = *(const float2*)(stg + (lr + 8) * SW + c + 8);
            uint32_t fh[4], fl[4];
            split_mask(v0.x, v0.y, fh[0], fl[0]);
            split_mask(v1.x, v1.y, fh[1], fl[1]);
            split_mask(v2.x, v2.y, fh[2], fl[2]);
            split_mask(v3.x, v3.y, fh[3], fl[3]);
#pragma unroll
            for (int g = 0; g < 2; g++) {
                uint32_t b[4][4];
#pragma unroll
                for (int jj = 0; jj < 4; jj++)
                    ldsm4(w1b + (16 * (4 * g + jj) * SA + 16 * s) * 2,
                          b[jj][0], b[jj][1], b[jj][2], b[jj][3]);
#pragma unroll
                for (int jj = 0; jj < 4; jj++) {
                    mma16816(acc[2 * (4 * g + jj)],     fh, b[jj][0], b[jj][1]);
                    mma16816(acc[2 * (4 * g + jj) + 1], fh, b[jj][2], b[jj][3]);
                }
#pragma unroll
                for (int jj = 0; jj < 4; jj++) {
                    mma16816(acc[2 * (4 * g + jj)],     fl, b[jj][0], b[jj][1]);
                    mma16816(acc[2 * (4 * g + jj) + 1], fl, b[jj][2], b[jj][3]);
                }
            }
        }
        __syncwarp();
        if (st + stride < num_strips) prefetch(st + stride);

        // ---- L1 epilogue: relu + split -> ah/al (bias already in acc) ------
        uint32_t ah[8][4], al[8][4];
#pragma unroll
        for (int j = 0; j < 16; j++) {
            float c0 = fmaxf(acc[j][0], 0.f), c1 = fmaxf(acc[j][1], 0.f);
            float c2 = fmaxf(acc[j][2], 0.f), c3 = fmaxf(acc[j][3], 0.f);
            const int s = j >> 1, o = (j & 1) * 2;
            split_mask(c0, c1, ah[s][o], al[s][o]);
            split_mask(c2, c3, ah[s][o + 1], al[s][o + 1]);
        }

        // ---- merged layers 2+3: chunk j2 of L2 output == L3 k-step j2 ------
        float acc3[4][4];
#pragma unroll
        for (int j = 0; j < 4; j++) {
            float2 bb = *(const float2*)(bs + 256 + 8 * j + lane4);
            acc3[j][0] = bb.x; acc3[j][1] = bb.y;
            acc3[j][2] = bb.x; acc3[j][3] = bb.y;
        }
#pragma unroll
        for (int j2 = 0; j2 < 8; j2++) {
            // L2 chunk: 16 output cols [16*j2, 16*j2+16)
            float a2[2][4];
#pragma unroll
            for (int h = 0; h < 2; h++) {
                float2 bb = *(const float2*)(bs + 128 + 8 * (2 * j2 + h) + lane4);
                a2[h][0] = bb.x; a2[h][1] = bb.y;
                a2[h][2] = bb.x; a2[h][3] = bb.y;
            }
#pragma unroll
            for (int s = 0; s < 8; s++) {
                uint32_t b0, b1, b2, b3;
                ldsm4(w2b + (16 * j2 * S2 + 16 * s) * 2, b0, b1, b2, b3);
                mma16816(a2[0], ah[s], b0, b1);
                mma16816(a2[1], ah[s], b2, b3);
                mma16816(a2[0], al[s], b0, b1);
                mma16816(a2[1], al[s], b2, b3);
            }
            // chunk epilogue: relu + split -> L3 A-fragment for k-step j2
            uint32_t fh[4], fl[4];
#pragma unroll
            for (int h = 0; h < 2; h++) {
                float c0 = fmaxf(a2[h][0], 0.f), c1 = fmaxf(a2[h][1], 0.f);
                float c2 = fmaxf(a2[h][2], 0.f), c3 = fmaxf(a2[h][3], 0.f);
                split_mask(c0, c1, fh[2 * h],     fl[2 * h]);
                split_mask(c2, c3, fh[2 * h + 1], fl[2 * h + 1]);
            }
            // L3 step s=j2 (n = 32 -> two 16-col ldsm groups)
            {
                uint32_t b0, b1, b2, b3;
                ldsm4(w3b + (16 * j2) * 2, b0, b1, b2, b3);
                mma16816(acc3[0], fh, b0, b1);
                mma16816(acc3[1], fh, b2, b3);
                mma16816(acc3[0], fl, b0, b1);
                mma16816(acc3[1], fl, b2, b3);
            }
            {
                uint32_t b0, b1, b2, b3;
                ldsm4(w3b + (16 * S2 + 16 * j2) * 2, b0, b1, b2, b3);
                mma16816(acc3[2], fh, b0, b1);
                mma16816(acc3[3], fh, b2, b3);
                mma16816(acc3[2], fl, b0, b1);
                mma16816(acc3[3], fl, b2, b3);
            }
        }

        // ---- store (bias already in acc3) ----------------------------------
#pragma unroll
        for (int j = 0; j < 4; j++) {
            *(float2*)(outp + r0 * 32 + 8 * j + lane4) =
                make_float2(acc3[j][0], acc3[j][1]);
            *(float2*)(outp + (r0 + 8) * 32 + 8 * j + lane4) =
                make_float2(acc3[j][2], acc3[j][3]);
        }
    }
}

// ---- SMEM layout (halves) --------------------------------------------------
#define O_SW1 0
#define O_SW2 5120       /* + 128*40  */
#define O_SW3 22528      /* + 128*136 */
#define O_JW1 26880      /* + 32*136  */
#define O_JW2 40192      /* + 128*104 */
#define O_JW3 57600      /* + 128*136 */
#define O_WEND 61952     /* + 32*136  */
#define O_ACT_B ((O_WEND * 2 + 576 * 4 + 15) & ~15)
#define SMEM_TOTAL (O_ACT_B + NW * 6400)

__global__ void init_bar_kernel() { g_arrive = 0; }

__global__ void __launch_bounds__(32 * NW, 1)
mlp_all(const float* __restrict__ leaf_feats,
        const float* __restrict__ internal_feats,
        const float* __restrict__ sW1, const float* __restrict__ sb1,
        const float* __restrict__ sW2, const float* __restrict__ sb2,
        const float* __restrict__ sW3, const float* __restrict__ sb3,
        const float* __restrict__ jW1, const float* __restrict__ jb1,
        const float* __restrict__ jW2, const float* __restrict__ jb2,
        const float* __restrict__ jW3, const float* __restrict__ jb3) {
    extern __shared__ __half sh[];
    float* bias = (float*)(sh + O_WEND);  // [0:288) leaf set, [288:576) join set
    const int tid = threadIdx.x;
    const int lane = tid & 31;
    const int wid = tid >> 5;
    constexpr int NT = 32 * NW;

    // ---- stage all weights (transposed Wt[n][k]) once ----------------------
    for (int idx = tid; idx < 128 * 32; idx += NT) {
        int nn = idx & 127, kk = idx >> 7;
        sh[O_SW1 + nn * 40 + kk] = __float2half(sW1[kk * 128 + nn]);
    }
    for (int idx = tid; idx < 128 * 128; idx += NT) {
        int nn = idx & 127, kk = idx >> 7;
        sh[O_SW2 + nn * 136 + kk] = __float2half(sW2[kk * 128 + nn]);
    }
    for (int idx = tid; idx < 32 * 128; idx += NT) {
        int nn = idx & 31, kk = idx >> 5;
        sh[O_SW3 + nn * 136 + kk] = __float2half(sW3[kk * 32 + nn]);
    }
    for (int idx = tid; idx < 128 * 96; idx += NT) {
        int nn = idx & 127, kk = idx >> 7;
        sh[O_JW1 + nn * 104 + kk] = __float2half(jW1[kk * 128 + nn]);
    }
    for (int idx = tid; idx < 128 * 128; idx += NT) {
        int nn = idx & 127, kk = idx >> 7;
        sh[O_JW2 + nn * 136 + kk] = __float2half(jW2[kk * 128 + nn]);
    }
    for (int idx = tid; idx < 32 * 128; idx += NT) {
        int nn = idx & 31, kk = idx >> 5;
        sh[O_JW3 + nn * 136 + kk] = __float2half(jW3[kk * 32 + nn]);
    }
    if (tid < 128) {
        bias[tid] = sb1[tid];       bias[128 + tid] = sb2[tid];
        bias[288 + tid] = jb1[tid]; bias[288 + 128 + tid] = jb2[tid];
    }
    if (tid < 32) { bias[256 + tid] = sb3[tid]; bias[288 + 256 + tid] = jb3[tid]; }
    __syncthreads();

    const uint32_t sb = smem_u32(sh);
    float* stg = (float*)((char*)sh + O_ACT_B) + (size_t)wid * 1600;
    const uint32_t stg_u32 = smem_u32(stg);

    // ---- level 0: leaf -----------------------------------------------------
    run_level<32>(leaf_feats, nullptr, g_bufA, NLEAF, 10, 0,
                  (BATCH * NLEAF) / 16, sb, O_SW1, O_SW2, O_SW3,
                  bias, stg, stg_u32, lane);
    int barno = 1;
    grid_bar(barno++);

    // ---- levels 1..10: joins ----------------------------------------------
    const float* pv = g_bufA;
    float* cr = g_bufB;
    int off = 0;
#pragma unroll 1
    for (int n = NLEAF / 2, ln = 9; n >= 1; n >>= 1, --ln) {
        run_level<96>(internal_feats, pv, cr, n, ln, off,
                      (BATCH * n) / 16, sb, O_JW1, O_JW2, O_JW3,
                      bias + 288, stg, stg_u32, lane);
        grid_bar(barno++);
        off += n;
        float* t = cr; cr = (float*)pv; pv = t;
    }
}

__global__ void gather_kernel(const float* __restrict__ src, float* __restrict__ dst) {
    int i = blockIdx.x * blockDim.x + threadIdx.x;
    if (i < BATCH) dst[i] = src[(long)i * 32];
}

extern "C" void kernel_launch(void* const* d_in, const int* in_sizes, int n_in,
                              void* d_out, int out_size) {
    (void)in_sizes; (void)n_in; (void)out_size;
    const float* leaf_feats     = (const float*)d_in[0];
    const float* internal_feats = (const float*)d_in[1];
    const float* sW1 = (const float*)d_in[2];
    const float* sb1 = (const float*)d_in[3];
    const float* sW2 = (const float*)d_in[4];
    const float* sb2 = (const float*)d_in[5];
    const float* sW3 = (const float*)d_in[6];
    const float* sb3 = (const float*)d_in[7];
    const float* jW1 = (const float*)d_in[8];
    const float* jb1 = (const float*)d_in[9];
    const float* jW2 = (const float*)d_in[10];
    const float* jb2 = (const float*)d_in[11];
    const float* jW3 = (const float*)d_in[12];
    const float* jb3 = (const float*)d_in[13];
    float* out = (float*)d_out;

    float* pa = nullptr;
    cudaGetSymbolAddress((void**)&pa, g_bufA);  // 10 swaps -> final output in bufA

    int dev = 0, sms = 148;
    cudaGetDevice(&dev);
    cudaDeviceGetAttribute(&sms, cudaDevAttrMultiProcessorCount, dev);

    cudaFuncSetAttribute(mlp_all, cudaFuncAttributeMaxDynamicSharedMemorySize,
                         SMEM_TOTAL);

    init_bar_kernel<<<1, 1>>>();
    mlp_all<<<sms, 32 * NW, SMEM_TOTAL>>>(leaf_feats, internal_feats,
                                          sW1, sb1, sW2, sb2, sW3, sb3,
                                          jW1, jb1, jW2, jb2, jW3, jb3);
    gather_kernel<<<(BATCH + 255) / 256, 256>>>(pa, out);
}